// round 15
// baseline (speedup 1.0000x reference)
#include <cuda_runtime.h>
#include <cuda_bf16.h>
#include <cstdint>
#include <math.h>

#define NUM_HEADS 16
#define HEAD 64
#define HIDDEN 1024
#define BATCH 4
#define TT 2048
#define TS 2048
// Q pre-scale: (1/sqrt(64)) * log2(e)  -> scores come out in log2 domain
#define QSCALE 0.18033688f
#define SM_SHIFT 8.0f

// ---------------------------------------------------------------------------
// Scratch (bf16 packed as uint32 pairs)
// ---------------------------------------------------------------------------
__device__ __align__(16) uint32_t g_xh[3][4194304];   // X bf16 (8192x1024)
__device__ __align__(16) uint32_t g_wh[3][524288];    // W bf16 (1024x1024)
__device__ __align__(16) uint32_t g_qhB[4194304];     // (b,h,t,d) Q bf16 pre-scaled
__device__ __align__(16) uint32_t g_khB[4194304];     // K bf16
__device__ __align__(16) uint32_t g_vhB[4194304];     // V bf16
__device__ int g_dummy_sink;

// ---------------------------------------------------------------------------
// helpers
// ---------------------------------------------------------------------------
__device__ __forceinline__ uint32_t smem_u32(const void* p) {
    uint32_t a;
    asm("{ .reg .u64 t; cvta.to.shared.u64 t, %1; cvt.u32.u64 %0, t; }"
        : "=r"(a) : "l"(p));
    return a;
}

__device__ __forceinline__ void ldm_x4(uint32_t r[4], uint32_t addr) {
    asm volatile("ldmatrix.sync.aligned.m8n8.x4.shared.b16 {%0,%1,%2,%3}, [%4];"
                 : "=r"(r[0]), "=r"(r[1]), "=r"(r[2]), "=r"(r[3]) : "r"(addr));
}

__device__ __forceinline__ void ldm_x4_t(uint32_t r[4], uint32_t addr) {
    asm volatile("ldmatrix.sync.aligned.m8n8.x4.trans.shared.b16 {%0,%1,%2,%3}, [%4];"
                 : "=r"(r[0]), "=r"(r[1]), "=r"(r[2]), "=r"(r[3]) : "r"(addr));
}

__device__ __forceinline__ void mma_bf16(float c[4], const uint32_t a[4],
                                         uint32_t b0, uint32_t b1) {
    asm volatile(
        "mma.sync.aligned.m16n8k16.row.col.f32.bf16.bf16.f32 "
        "{%0,%1,%2,%3}, {%4,%5,%6,%7}, {%8,%9}, {%0,%1,%2,%3};"
        : "+f"(c[0]), "+f"(c[1]), "+f"(c[2]), "+f"(c[3])
        : "r"(a[0]), "r"(a[1]), "r"(a[2]), "r"(a[3]), "r"(b0), "r"(b1));
}

__device__ __forceinline__ uint32_t pack_rn(float x, float y) {
    __nv_bfloat162 h2 = __floats2bfloat162_rn(x, y);
    return *(uint32_t*)&h2;
}

__device__ __forceinline__ float ex2(float x) {
    float y;
    asm("ex2.approx.f32 %0, %1;" : "=f"(y) : "f"(x));
    return y;
}

__device__ __forceinline__ void cp16(uint32_t dst, const void* src) {
    asm volatile("cp.async.cg.shared.global [%0], [%1], 16;"
                 :: "r"(dst), "l"(src));
}
#define CP_COMMIT() asm volatile("cp.async.commit_group;" ::: "memory")
#define CP_WAIT(N)  asm volatile("cp.async.wait_group %0;" :: "n"(N) : "memory")

// ---------------------------------------------------------------------------
// Pad kernels: keep the ncu capture slot (launch index 3) on proj.
// ---------------------------------------------------------------------------
__global__ void sched_pad_kernel() {
    if (threadIdx.x == 0) g_dummy_sink = 1;
}
__global__ void sched_pad_kernel2() {
    if (threadIdx.x == 0) g_dummy_sink = 2;
}

// ---------------------------------------------------------------------------
// Split pass: fp32 -> bf16 (quantize only)
// ---------------------------------------------------------------------------
__global__ void split_kernel(const float* __restrict__ q, const float* __restrict__ k,
                             const float* __restrict__ v, const float* __restrict__ Wq,
                             const float* __restrict__ Wk, const float* __restrict__ Wv)
{
    const int z = blockIdx.z;
    const float* src;
    uint32_t* hdst;
    size_t n4;
    if (z < 3) {
        src = (z == 0) ? q : (z == 1) ? k : v;
        hdst = g_xh[z];
        n4 = (size_t)8192 * 1024 / 4;
    } else {
        int j = z - 3;
        src = (j == 0) ? Wq : (j == 1) ? Wk : Wv;
        hdst = g_wh[j];
        n4 = (size_t)1024 * 1024 / 4;
    }
    const float4* s4 = (const float4*)src;
    size_t stride = (size_t)gridDim.x * blockDim.x;
    for (size_t i = (size_t)blockIdx.x * blockDim.x + threadIdx.x; i < n4;
         i += 2 * stride) {
        float4 a = s4[i];
        size_t i2 = i + stride;
        bool ok2 = (i2 < n4);
        float4 b = ok2 ? s4[i2] : make_float4(0.f, 0.f, 0.f, 0.f);
        *(uint2*)(hdst + i * 2) = make_uint2(pack_rn(a.x, a.y), pack_rn(a.z, a.w));
        if (ok2)
            *(uint2*)(hdst + i2 * 2) = make_uint2(pack_rn(b.x, b.y), pack_rn(b.z, b.w));
    }
}

// ---------------------------------------------------------------------------
// Projection v2: C = relu6(Xh @ Wh^T + bias)
// 4 warps x (64x64) warp tiles (attn's measured-better mix: 0.25 ldm/MMA,
// 128 MMA per barrier). K-chunk 64, 3-stage cp.async ring, distance 2.
// Per-element K accumulation order unchanged.
// ---------------------------------------------------------------------------
#define PROWB 144
#define P_AH  0
#define P_BH  (128 * PROWB)           // 18432
#define PBUF  (2 * 128 * PROWB)       // 36864
#define PROJ_SMEM (3 * PBUF)          // 110592

__global__ __launch_bounds__(128, 2) void proj_mma_kernel(
    const float* __restrict__ bq, const float* __restrict__ bk,
    const float* __restrict__ bv)
{
    extern __shared__ char sbp[];
    const uint32_t sb = smem_u32(sbp);

    const int z = blockIdx.z;
    const uint32_t* Xh = g_xh[z];
    const uint32_t* Wh = g_wh[z];
    const float* bias = (z == 0) ? bq : (z == 1) ? bk : bv;

    const int tid  = threadIdx.x;
    const int lane = tid & 31;
    const int wid  = tid >> 5;
    const int wm   = wid >> 1;        // 0..1 -> m offset wm*64
    const int wn   = wid & 1;         // 0..1 -> n offset wn*64
    const int m0   = blockIdx.y * 128;
    const int n0   = blockIdx.x * 128;
    const int fr   = lane & 15;
    const int fc2  = (lane >> 4) * 16;

    float acc[4][8][4];
    #pragma unroll
    for (int i = 0; i < 4; i++)
        #pragma unroll
        for (int j = 0; j < 8; j++)
            #pragma unroll
            for (int e = 0; e < 4; e++) acc[i][j][e] = 0.f;

    // chunk = 64 floats = 128B per row; A rows 0-127, B rows 0-127.
    // 128 threads x 16 cp16 = 2048 loads covering both tiles.
    auto load_chunk = [&](int c) {
        const uint32_t dst = sb + (c % 3) * PBUF;
        const int k2 = c * 32;
        #pragma unroll
        for (int it = 0; it < 8; it++) {
            int idx = it * 128 + tid;
            int row = idx >> 3, seg = idx & 7;
            uint32_t soff = row * PROWB + seg * 16;
            cp16(dst + P_AH + soff, Xh + (size_t)(m0 + row) * 512 + k2 + seg * 4);
            cp16(dst + P_BH + soff, Wh + (size_t)(n0 + row) * 512 + k2 + seg * 4);
        }
        CP_COMMIT();
    };

    const int NC = HIDDEN / 64;   // 16
    load_chunk(0);
    load_chunk(1);

    for (int c = 0; c < NC; c++) {
        if (c < NC - 1) { CP_WAIT(1); } else { CP_WAIT(0); }
        __syncthreads();
        if (c + 2 < NC) load_chunk(c + 2);

        const uint32_t bufb = sb + (c % 3) * PBUF;
        #pragma unroll
        for (int ks = 0; ks < 4; ks++) {
            const uint32_t kbyte = ks * 32 + fc2;

            uint32_t bhf[8][2];
            #pragma unroll
            for (int nb = 0; nb < 4; nb++) {
                uint32_t row = wn * 64 + nb * 16 + fr;
                uint32_t t4[4];
                ldm_x4(t4, bufb + P_BH + row * PROWB + kbyte);
                bhf[2 * nb][0] = t4[0]; bhf[2 * nb][1] = t4[2];
                bhf[2 * nb + 1][0] = t4[1]; bhf[2 * nb + 1][1] = t4[3];
            }

            #pragma unroll
            for (int mi = 0; mi < 4; mi++) {
                uint32_t row = wm * 64 + mi * 16 + fr;
                uint32_t ah[4];
                ldm_x4(ah, bufb + P_AH + row * PROWB + kbyte);
                #pragma unroll
                for (int f = 0; f < 8; f++)
                    mma_bf16(acc[mi][f], ah, bhf[f][0], bhf[f][1]);
            }
        }
    }

    // epilogue: bias + relu6 -> bf16 scratch (Q pre-scaled into log2 domain)
    const int qrow = lane >> 2;
    const int qcol = (lane & 3) * 2;
    #pragma unroll
    for (int mi = 0; mi < 4; mi++) {
        #pragma unroll
        for (int f = 0; f < 8; f++) {
            int colg = n0 + wn * 64 + f * 8 + qcol;
            float b0v = __ldg(bias + colg);
            float b1v = __ldg(bias + colg + 1);
            int h = colg >> 6, d = colg & 63;
            #pragma unroll
            for (int half = 0; half < 2; half++) {
                int m = m0 + wm * 64 + mi * 16 + qrow + half * 8;
                int t = m >> 2, bb = m & 3;
                float y0 = acc[mi][f][half * 2 + 0] + b0v;
                float y1 = acc[mi][f][half * 2 + 1] + b1v;
                y0 = fminf(fmaxf(y0, 0.f), 6.f);
                y1 = fminf(fmaxf(y1, 0.f), 6.f);
                size_t o2 = (((size_t)bb * NUM_HEADS + h) * TT + t) * 32 + (d >> 1);
                if (z == 0)      g_qhB[o2] = pack_rn(y0 * QSCALE, y1 * QSCALE);
                else if (z == 1) g_khB[o2] = pack_rn(y0, y1);
                else             g_vhB[o2] = pack_rn(y0, y1);
            }
        }
    }
}

// ---------------------------------------------------------------------------
// Flash attention v3 (unchanged from R13): 4 warps x 32 q-rows, Q fragments
// in registers, 3-stage KV ring, prefetch distance 2.
// ---------------------------------------------------------------------------
#define AROWB 144
#define SQ_OFF 0
#define KV_BASE (128 * AROWB)              // 18432
#define KVBUF (2 * 64 * AROWB)             // 18432 (K + V one stage)
#define ATTN_SMEM (KV_BASE + 3 * KVBUF)    // 73728

__global__ __launch_bounds__(128, 3) void attn_mma_kernel(float* __restrict__ out)
{
    extern __shared__ char sm[];
    const uint32_t sb = smem_u32(sm);

    const int bh = blockIdx.y;
    const int b  = bh >> 4;
    const int h  = bh & 15;
    const int q0 = blockIdx.x * 128;

    const uint32_t* Qg  = g_qhB + (size_t)bh * TT * 32;
    const uint32_t* Khg = g_khB + (size_t)bh * TS * 32;
    const uint32_t* Vhg = g_vhB + (size_t)bh * TS * 32;

    const int tid  = threadIdx.x;
    const int lane = tid & 31;
    const int w    = tid >> 5;
    const int fr   = lane & 15;
    const int fc   = (lane >> 4) * 16;

    #pragma unroll
    for (int it = 0; it < 8; it++) {
        int idx = it * 128 + tid;
        int row = idx >> 3, seg = idx & 7;
        uint4 vq = *(const uint4*)(Qg + (size_t)(q0 + row) * 32 + seg * 4);
        *(uint4*)(sm + SQ_OFF + row * AROWB + seg * 16) = vq;
    }

    auto load_tile = [&](int st) {
        const uint32_t dst = sb + KV_BASE + (st % 3) * KVBUF;
        const int s0 = st * 64;
        #pragma unroll
        for (int it = 0; it < 4; it++) {
            int idx = it * 128 + tid;
            int row = idx >> 3, seg = idx & 7;
            size_t goff = (size_t)(s0 + row) * 32 + seg * 4;
            uint32_t soff = row * AROWB + seg * 16;
            cp16(dst + 0 * 64 * AROWB + soff, Khg + goff);
            cp16(dst + 1 * 64 * AROWB + soff, Vhg + goff);
        }
        CP_COMMIT();
    };

    const int NT = TS / 64;
    load_tile(0);
    load_tile(1);

    __syncthreads();
    uint32_t qf[2][4][4];
    #pragma unroll
    for (int g = 0; g < 2; g++)
        #pragma unroll
        for (int ks = 0; ks < 4; ks++)
            ldm_x4(qf[g][ks],
                   sb + SQ_OFF + (w * 32 + g * 16 + fr) * AROWB + ks * 32 + fc);

    float o[2][8][4];
    #pragma unroll
    for (int mi = 0; mi < 2; mi++)
        #pragma unroll
        for (int j = 0; j < 8; j++)
            #pragma unroll
            for (int e = 0; e < 4; e++) o[mi][j][e] = 0.f;
    float ls[2][2] = {{0.f, 0.f}, {0.f, 0.f}};

    for (int st = 0; st < NT; st++) {
        if (st < NT - 1) { CP_WAIT(1); } else { CP_WAIT(0); }
        __syncthreads();
        if (st + 2 < NT) load_tile(st + 2);

        const uint32_t khb = sb + KV_BASE + (st % 3) * KVBUF;
        const uint32_t vhb = khb + 64 * AROWB;

        #pragma unroll
        for (int half = 0; half < 2; half++) {
            float sacc[2][4][4];
            #pragma unroll
            for (int mi = 0; mi < 2; mi++)
                #pragma unroll
                for (int j = 0; j < 4; j++)
                    #pragma unroll
                    for (int e = 0; e < 4; e++) sacc[mi][j][e] = 0.f;

            #pragma unroll
            for (int ks = 0; ks < 4; ks++) {
                #pragma unroll
                for (int njl = 0; njl < 2; njl++) {
                    uint32_t bh4[4];
                    ldm_x4(bh4, khb + (half * 32 + njl * 16 + fr) * AROWB + ks * 32 + fc);
                    mma_bf16(sacc[0][2 * njl],     qf[0][ks], bh4[0], bh4[2]);
                    mma_bf16(sacc[0][2 * njl + 1], qf[0][ks], bh4[1], bh4[3]);
                    mma_bf16(sacc[1][2 * njl],     qf[1][ks], bh4[0], bh4[2]);
                    mma_bf16(sacc[1][2 * njl + 1], qf[1][ks], bh4[1], bh4[3]);
                }
            }

            #pragma unroll
            for (int t = 0; t < 2; t++) {
                uint32_t vh4[4][4];
                #pragma unroll
                for (int nj = 0; nj < 4; nj++)
                    ldm_x4_t(vh4[nj],
                             vhb + (half * 32 + t * 16 + fr) * AROWB + nj * 32 + fc);

                #pragma unroll
                for (int mi = 0; mi < 2; mi++) {
                    float* s0p = sacc[mi][2 * t];
                    float* s1p = sacc[mi][2 * t + 1];
                    s0p[0] = ex2(s0p[0] - SM_SHIFT);
                    s0p[1] = ex2(s0p[1] - SM_SHIFT);
                    s0p[2] = ex2(s0p[2] - SM_SHIFT);
                    s0p[3] = ex2(s0p[3] - SM_SHIFT);
                    s1p[0] = ex2(s1p[0] - SM_SHIFT);
                    s1p[1] = ex2(s1p[1] - SM_SHIFT);
                    s1p[2] = ex2(s1p[2] - SM_SHIFT);
                    s1p[3] = ex2(s1p[3] - SM_SHIFT);
                    ls[mi][0] += s0p[0] + s0p[1] + s1p[0] + s1p[1];
                    ls[mi][1] += s0p[2] + s0p[3] + s1p[2] + s1p[3];

                    uint32_t ph[4];
                    ph[0] = pack_rn(s0p[0], s0p[1]);
                    ph[1] = pack_rn(s0p[2], s0p[3]);
                    ph[2] = pack_rn(s1p[0], s1p[1]);
                    ph[3] = pack_rn(s1p[2], s1p[3]);

                    #pragma unroll
                    for (int nj = 0; nj < 4; nj++) {
                        mma_bf16(o[mi][2 * nj],     ph, vh4[nj][0], vh4[nj][1]);
                        mma_bf16(o[mi][2 * nj + 1], ph, vh4[nj][2], vh4[nj][3]);
                    }
                }
            }
        }
    }

    #pragma unroll
    for (int mi = 0; mi < 2; mi++) {
        ls[mi][0] += __shfl_xor_sync(0xffffffffu, ls[mi][0], 1);
        ls[mi][0] += __shfl_xor_sync(0xffffffffu, ls[mi][0], 2);
        ls[mi][1] += __shfl_xor_sync(0xffffffffu, ls[mi][1], 1);
        ls[mi][1] += __shfl_xor_sync(0xffffffffu, ls[mi][1], 2);
        float inv0 = 1.f / ls[mi][0], inv1 = 1.f / ls[mi][1];
        int row0 = q0 + w * 32 + mi * 16 + (lane >> 2);
        int row1 = row0 + 8;
        #pragma unroll
        for (int j = 0; j < 8; j++) {
            int col = h * HEAD + j * 8 + (lane & 3) * 2;
            *(float2*)(out + ((size_t)row0 * BATCH + b) * HIDDEN + col) =
                make_float2(o[mi][j][0] * inv0, o[mi][j][1] * inv0);
            *(float2*)(out + ((size_t)row1 * BATCH + b) * HIDDEN + col) =
                make_float2(o[mi][j][2] * inv1, o[mi][j][3] * inv1);
        }
    }
}

// ---------------------------------------------------------------------------
extern "C" void kernel_launch(void* const* d_in, const int* in_sizes, int n_in,
                              void* d_out, int out_size)
{
    const float* q  = (const float*)d_in[0];
    const float* k  = (const float*)d_in[1];
    const float* v  = (const float*)d_in[2];
    const float* Wq = (const float*)d_in[3];
    const float* bq = (const float*)d_in[4];
    const float* Wk = (const float*)d_in[5];
    const float* bk = (const float*)d_in[6];
    const float* Wv = (const float*)d_in[7];
    const float* bv = (const float*)d_in[8];
    float* out = (float*)d_out;

    cudaFuncSetAttribute(proj_mma_kernel,
                         cudaFuncAttributeMaxDynamicSharedMemorySize, PROJ_SMEM);
    cudaFuncSetAttribute(attn_mma_kernel,
                         cudaFuncAttributeMaxDynamicSharedMemorySize, ATTN_SMEM);

    // Two pads: ncu capture slot (launch index 3) lands on proj_mma_kernel.
    sched_pad_kernel<<<1, 32>>>();
    sched_pad_kernel2<<<1, 32>>>();

    dim3 gsplit(512, 1, 6);
    split_kernel<<<gsplit, 256>>>(q, k, v, Wq, Wk, Wv);

    dim3 gproj(HIDDEN / 128, (TT * BATCH) / 128, 3);
    proj_mma_kernel<<<gproj, 128, PROJ_SMEM>>>(bq, bk, bv);

    dim3 gattn(TT / 128, BATCH * NUM_HEADS);
    attn_mma_kernel<<<gattn, 128, ATTN_SMEM>>>(out);
}

// round 16
// speedup vs baseline: 1.0259x; 1.0259x over previous
#include <cuda_runtime.h>
#include <cuda_bf16.h>
#include <cstdint>
#include <math.h>

#define NUM_HEADS 16
#define HEAD 64
#define HIDDEN 1024
#define BATCH 4
#define TT 2048
#define TS 2048
// Q pre-scale: (1/sqrt(64)) * log2(e)  -> scores come out in log2 domain
#define QSCALE 0.18033688f
#define SM_SHIFT 8.0f

// ---------------------------------------------------------------------------
// Scratch (bf16 packed as uint32 pairs)
// ---------------------------------------------------------------------------
__device__ __align__(16) uint32_t g_xh[3][4194304];   // X bf16 (8192x1024)
__device__ __align__(16) uint32_t g_wh[3][524288];    // W bf16 (1024x1024)
__device__ __align__(16) uint32_t g_qhB[4194304];     // (b,h,t,d) Q bf16 pre-scaled
__device__ __align__(16) uint32_t g_khB[4194304];     // K bf16
__device__ __align__(16) uint32_t g_vhB[4194304];     // V bf16

// ---------------------------------------------------------------------------
// helpers
// ---------------------------------------------------------------------------
__device__ __forceinline__ uint32_t smem_u32(const void* p) {
    uint32_t a;
    asm("{ .reg .u64 t; cvta.to.shared.u64 t, %1; cvt.u32.u64 %0, t; }"
        : "=r"(a) : "l"(p));
    return a;
}

__device__ __forceinline__ void ldm_x4(uint32_t r[4], uint32_t addr) {
    asm volatile("ldmatrix.sync.aligned.m8n8.x4.shared.b16 {%0,%1,%2,%3}, [%4];"
                 : "=r"(r[0]), "=r"(r[1]), "=r"(r[2]), "=r"(r[3]) : "r"(addr));
}

__device__ __forceinline__ void ldm_x4_t(uint32_t r[4], uint32_t addr) {
    asm volatile("ldmatrix.sync.aligned.m8n8.x4.trans.shared.b16 {%0,%1,%2,%3}, [%4];"
                 : "=r"(r[0]), "=r"(r[1]), "=r"(r[2]), "=r"(r[3]) : "r"(addr));
}

__device__ __forceinline__ void mma_bf16(float c[4], const uint32_t a[4],
                                         uint32_t b0, uint32_t b1) {
    asm volatile(
        "mma.sync.aligned.m16n8k16.row.col.f32.bf16.bf16.f32 "
        "{%0,%1,%2,%3}, {%4,%5,%6,%7}, {%8,%9}, {%0,%1,%2,%3};"
        : "+f"(c[0]), "+f"(c[1]), "+f"(c[2]), "+f"(c[3])
        : "r"(a[0]), "r"(a[1]), "r"(a[2]), "r"(a[3]), "r"(b0), "r"(b1));
}

__device__ __forceinline__ uint32_t pack_rn(float x, float y) {
    __nv_bfloat162 h2 = __floats2bfloat162_rn(x, y);
    return *(uint32_t*)&h2;
}

__device__ __forceinline__ float ex2(float x) {
    float y;
    asm("ex2.approx.f32 %0, %1;" : "=f"(y) : "f"(x));
    return y;
}

__device__ __forceinline__ void cp16(uint32_t dst, const void* src) {
    asm volatile("cp.async.cg.shared.global [%0], [%1], 16;"
                 :: "r"(dst), "l"(src));
}
#define CP_COMMIT() asm volatile("cp.async.commit_group;" ::: "memory")
#define CP_WAIT(N)  asm volatile("cp.async.wait_group %0;" :: "n"(N) : "memory")

// ---------------------------------------------------------------------------
// Split pass: fp32 -> bf16 (quantize only)
// ---------------------------------------------------------------------------
__global__ void split_kernel(const float* __restrict__ q, const float* __restrict__ k,
                             const float* __restrict__ v, const float* __restrict__ Wq,
                             const float* __restrict__ Wk, const float* __restrict__ Wv)
{
    const int z = blockIdx.z;
    const float* src;
    uint32_t* hdst;
    size_t n4;
    if (z < 3) {
        src = (z == 0) ? q : (z == 1) ? k : v;
        hdst = g_xh[z];
        n4 = (size_t)8192 * 1024 / 4;
    } else {
        int j = z - 3;
        src = (j == 0) ? Wq : (j == 1) ? Wk : Wv;
        hdst = g_wh[j];
        n4 = (size_t)1024 * 1024 / 4;
    }
    const float4* s4 = (const float4*)src;
    size_t stride = (size_t)gridDim.x * blockDim.x;
    for (size_t i = (size_t)blockIdx.x * blockDim.x + threadIdx.x; i < n4;
         i += 2 * stride) {
        float4 a = s4[i];
        size_t i2 = i + stride;
        bool ok2 = (i2 < n4);
        float4 b = ok2 ? s4[i2] : make_float4(0.f, 0.f, 0.f, 0.f);
        *(uint2*)(hdst + i * 2) = make_uint2(pack_rn(a.x, a.y), pack_rn(a.z, a.w));
        if (ok2)
            *(uint2*)(hdst + i2 * 2) = make_uint2(pack_rn(b.x, b.y), pack_rn(b.z, b.w));
    }
}

// ---------------------------------------------------------------------------
// Projection (R14 known-best): C = relu6(Xh @ Wh^T + bias)
// 8 warps x (64x32) warp tiles, K-chunk 64 (128B rows, 144B stride),
// 3-stage cp.async ring, prefetch distance 2.
// ---------------------------------------------------------------------------
#define PROWB 144
#define P_AH  0
#define P_BH  (128 * PROWB)           // 18432
#define PBUF  (2 * 128 * PROWB)       // 36864
#define PROJ_SMEM (3 * PBUF)          // 110592

__global__ __launch_bounds__(256, 2) void proj_mma_kernel(
    const float* __restrict__ bq, const float* __restrict__ bk,
    const float* __restrict__ bv)
{
    extern __shared__ char sbp[];
    const uint32_t sb = smem_u32(sbp);

    const int z = blockIdx.z;
    const uint32_t* Xh = g_xh[z];
    const uint32_t* Wh = g_wh[z];
    const float* bias = (z == 0) ? bq : (z == 1) ? bk : bv;

    const int tid  = threadIdx.x;
    const int lane = tid & 31;
    const int wid  = tid >> 5;
    const int wm   = wid >> 2;
    const int wn   = wid & 3;
    const int m0   = blockIdx.y * 128;
    const int n0   = blockIdx.x * 128;
    const int fr   = lane & 15;
    const int fc2  = (lane >> 4) * 16;

    float acc[4][4][4];
    #pragma unroll
    for (int i = 0; i < 4; i++)
        #pragma unroll
        for (int j = 0; j < 4; j++)
            #pragma unroll
            for (int e = 0; e < 4; e++) acc[i][j][e] = 0.f;

    auto load_chunk = [&](int c) {
        const uint32_t dst = sb + (c % 3) * PBUF;
        const int k2 = c * 32;
        #pragma unroll
        for (int it = 0; it < 4; it++) {
            int idx = it * 256 + tid;
            int row = idx >> 3, seg = idx & 7;
            uint32_t soff = row * PROWB + seg * 16;
            cp16(dst + P_AH + soff, Xh + (size_t)(m0 + row) * 512 + k2 + seg * 4);
            cp16(dst + P_BH + soff, Wh + (size_t)(n0 + row) * 512 + k2 + seg * 4);
        }
        CP_COMMIT();
    };

    const int NC = HIDDEN / 64;   // 16
    load_chunk(0);
    load_chunk(1);

    for (int c = 0; c < NC; c++) {
        if (c < NC - 1) { CP_WAIT(1); } else { CP_WAIT(0); }
        __syncthreads();
        if (c + 2 < NC) load_chunk(c + 2);

        const uint32_t bufb = sb + (c % 3) * PBUF;
        #pragma unroll
        for (int ks = 0; ks < 4; ks++) {
            const uint32_t kbyte = ks * 32 + fc2;

            uint32_t bhf[4][2];
            #pragma unroll
            for (int nj = 0; nj < 2; nj++) {
                uint32_t row = wn * 32 + nj * 16 + fr;
                uint32_t t4[4];
                ldm_x4(t4, bufb + P_BH + row * PROWB + kbyte);
                bhf[2 * nj][0] = t4[0]; bhf[2 * nj][1] = t4[2];
                bhf[2 * nj + 1][0] = t4[1]; bhf[2 * nj + 1][1] = t4[3];
            }

            #pragma unroll
            for (int mi = 0; mi < 4; mi++) {
                uint32_t row = wm * 64 + mi * 16 + fr;
                uint32_t ah[4];
                ldm_x4(ah, bufb + P_AH + row * PROWB + kbyte);
                #pragma unroll
                for (int f = 0; f < 4; f++)
                    mma_bf16(acc[mi][f], ah, bhf[f][0], bhf[f][1]);
            }
        }
    }

    // epilogue: bias + relu6 -> bf16 scratch (Q pre-scaled into log2 domain)
    const int qrow = lane >> 2;
    const int qcol = (lane & 3) * 2;
    #pragma unroll
    for (int mi = 0; mi < 4; mi++) {
        #pragma unroll
        for (int f = 0; f < 4; f++) {
            int colg = n0 + wn * 32 + f * 8 + qcol;
            float b0v = __ldg(bias + colg);
            float b1v = __ldg(bias + colg + 1);
            int h = colg >> 6, d = colg & 63;
            #pragma unroll
            for (int half = 0; half < 2; half++) {
                int m = m0 + wm * 64 + mi * 16 + qrow + half * 8;
                int t = m >> 2, bb = m & 3;
                float y0 = acc[mi][f][half * 2 + 0] + b0v;
                float y1 = acc[mi][f][half * 2 + 1] + b1v;
                y0 = fminf(fmaxf(y0, 0.f), 6.f);
                y1 = fminf(fmaxf(y1, 0.f), 6.f);
                size_t o2 = (((size_t)bb * NUM_HEADS + h) * TT + t) * 32 + (d >> 1);
                if (z == 0)      g_qhB[o2] = pack_rn(y0 * QSCALE, y1 * QSCALE);
                else if (z == 1) g_khB[o2] = pack_rn(y0, y1);
                else             g_vhB[o2] = pack_rn(y0, y1);
            }
        }
    }
}

// ---------------------------------------------------------------------------
// Flash attention v3 (R13 known-best): 4 warps x 32 q-rows, Q fragments in
// registers, 3-stage KV ring, prefetch distance 2.
// ---------------------------------------------------------------------------
#define AROWB 144
#define SQ_OFF 0
#define KV_BASE (128 * AROWB)              // 18432
#define KVBUF (2 * 64 * AROWB)             // 18432 (K + V one stage)
#define ATTN_SMEM (KV_BASE + 3 * KVBUF)    // 73728

__global__ __launch_bounds__(128, 3) void attn_mma_kernel(float* __restrict__ out)
{
    extern __shared__ char sm[];
    const uint32_t sb = smem_u32(sm);

    const int bh = blockIdx.y;
    const int b  = bh >> 4;
    const int h  = bh & 15;
    const int q0 = blockIdx.x * 128;

    const uint32_t* Qg  = g_qhB + (size_t)bh * TT * 32;
    const uint32_t* Khg = g_khB + (size_t)bh * TS * 32;
    const uint32_t* Vhg = g_vhB + (size_t)bh * TS * 32;

    const int tid  = threadIdx.x;
    const int lane = tid & 31;
    const int w    = tid >> 5;
    const int fr   = lane & 15;
    const int fc   = (lane >> 4) * 16;

    #pragma unroll
    for (int it = 0; it < 8; it++) {
        int idx = it * 128 + tid;
        int row = idx >> 3, seg = idx & 7;
        uint4 vq = *(const uint4*)(Qg + (size_t)(q0 + row) * 32 + seg * 4);
        *(uint4*)(sm + SQ_OFF + row * AROWB + seg * 16) = vq;
    }

    auto load_tile = [&](int st) {
        const uint32_t dst = sb + KV_BASE + (st % 3) * KVBUF;
        const int s0 = st * 64;
        #pragma unroll
        for (int it = 0; it < 4; it++) {
            int idx = it * 128 + tid;
            int row = idx >> 3, seg = idx & 7;
            size_t goff = (size_t)(s0 + row) * 32 + seg * 4;
            uint32_t soff = row * AROWB + seg * 16;
            cp16(dst + 0 * 64 * AROWB + soff, Khg + goff);
            cp16(dst + 1 * 64 * AROWB + soff, Vhg + goff);
        }
        CP_COMMIT();
    };

    const int NT = TS / 64;
    load_tile(0);
    load_tile(1);

    __syncthreads();
    uint32_t qf[2][4][4];
    #pragma unroll
    for (int g = 0; g < 2; g++)
        #pragma unroll
        for (int ks = 0; ks < 4; ks++)
            ldm_x4(qf[g][ks],
                   sb + SQ_OFF + (w * 32 + g * 16 + fr) * AROWB + ks * 32 + fc);

    float o[2][8][4];
    #pragma unroll
    for (int mi = 0; mi < 2; mi++)
        #pragma unroll
        for (int j = 0; j < 8; j++)
            #pragma unroll
            for (int e = 0; e < 4; e++) o[mi][j][e] = 0.f;
    float ls[2][2] = {{0.f, 0.f}, {0.f, 0.f}};

    for (int st = 0; st < NT; st++) {
        if (st < NT - 1) { CP_WAIT(1); } else { CP_WAIT(0); }
        __syncthreads();
        if (st + 2 < NT) load_tile(st + 2);

        const uint32_t khb = sb + KV_BASE + (st % 3) * KVBUF;
        const uint32_t vhb = khb + 64 * AROWB;

        #pragma unroll
        for (int half = 0; half < 2; half++) {
            float sacc[2][4][4];
            #pragma unroll
            for (int mi = 0; mi < 2; mi++)
                #pragma unroll
                for (int j = 0; j < 4; j++)
                    #pragma unroll
                    for (int e = 0; e < 4; e++) sacc[mi][j][e] = 0.f;

            #pragma unroll
            for (int ks = 0; ks < 4; ks++) {
                #pragma unroll
                for (int njl = 0; njl < 2; njl++) {
                    uint32_t bh4[4];
                    ldm_x4(bh4, khb + (half * 32 + njl * 16 + fr) * AROWB + ks * 32 + fc);
                    mma_bf16(sacc[0][2 * njl],     qf[0][ks], bh4[0], bh4[2]);
                    mma_bf16(sacc[0][2 * njl + 1], qf[0][ks], bh4[1], bh4[3]);
                    mma_bf16(sacc[1][2 * njl],     qf[1][ks], bh4[0], bh4[2]);
                    mma_bf16(sacc[1][2 * njl + 1], qf[1][ks], bh4[1], bh4[3]);
                }
            }

            #pragma unroll
            for (int t = 0; t < 2; t++) {
                uint32_t vh4[4][4];
                #pragma unroll
                for (int nj = 0; nj < 4; nj++)
                    ldm_x4_t(vh4[nj],
                             vhb + (half * 32 + t * 16 + fr) * AROWB + nj * 32 + fc);

                #pragma unroll
                for (int mi = 0; mi < 2; mi++) {
                    float* s0p = sacc[mi][2 * t];
                    float* s1p = sacc[mi][2 * t + 1];
                    s0p[0] = ex2(s0p[0] - SM_SHIFT);
                    s0p[1] = ex2(s0p[1] - SM_SHIFT);
                    s0p[2] = ex2(s0p[2] - SM_SHIFT);
                    s0p[3] = ex2(s0p[3] - SM_SHIFT);
                    s1p[0] = ex2(s1p[0] - SM_SHIFT);
                    s1p[1] = ex2(s1p[1] - SM_SHIFT);
                    s1p[2] = ex2(s1p[2] - SM_SHIFT);
                    s1p[3] = ex2(s1p[3] - SM_SHIFT);
                    ls[mi][0] += s0p[0] + s0p[1] + s1p[0] + s1p[1];
                    ls[mi][1] += s0p[2] + s0p[3] + s1p[2] + s1p[3];

                    uint32_t ph[4];
                    ph[0] = pack_rn(s0p[0], s0p[1]);
                    ph[1] = pack_rn(s0p[2], s0p[3]);
                    ph[2] = pack_rn(s1p[0], s1p[1]);
                    ph[3] = pack_rn(s1p[2], s1p[3]);

                    #pragma unroll
                    for (int nj = 0; nj < 4; nj++) {
                        mma_bf16(o[mi][2 * nj],     ph, vh4[nj][0], vh4[nj][1]);
                        mma_bf16(o[mi][2 * nj + 1], ph, vh4[nj][2], vh4[nj][3]);
                    }
                }
            }
        }
    }

    #pragma unroll
    for (int mi = 0; mi < 2; mi++) {
        ls[mi][0] += __shfl_xor_sync(0xffffffffu, ls[mi][0], 1);
        ls[mi][0] += __shfl_xor_sync(0xffffffffu, ls[mi][0], 2);
        ls[mi][1] += __shfl_xor_sync(0xffffffffu, ls[mi][1], 1);
        ls[mi][1] += __shfl_xor_sync(0xffffffffu, ls[mi][1], 2);
        float inv0 = 1.f / ls[mi][0], inv1 = 1.f / ls[mi][1];
        int row0 = q0 + w * 32 + mi * 16 + (lane >> 2);
        int row1 = row0 + 8;
        #pragma unroll
        for (int j = 0; j < 8; j++) {
            int col = h * HEAD + j * 8 + (lane & 3) * 2;
            *(float2*)(out + ((size_t)row0 * BATCH + b) * HIDDEN + col) =
                make_float2(o[mi][j][0] * inv0, o[mi][j][1] * inv0);
            *(float2*)(out + ((size_t)row1 * BATCH + b) * HIDDEN + col) =
                make_float2(o[mi][j][2] * inv1, o[mi][j][3] * inv1);
        }
    }
}

// ---------------------------------------------------------------------------
extern "C" void kernel_launch(void* const* d_in, const int* in_sizes, int n_in,
                              void* d_out, int out_size)
{
    const float* q  = (const float*)d_in[0];
    const float* k  = (const float*)d_in[1];
    const float* v  = (const float*)d_in[2];
    const float* Wq = (const float*)d_in[3];
    const float* bq = (const float*)d_in[4];
    const float* Wk = (const float*)d_in[5];
    const float* bk = (const float*)d_in[6];
    const float* Wv = (const float*)d_in[7];
    const float* bv = (const float*)d_in[8];
    float* out = (float*)d_out;

    cudaFuncSetAttribute(proj_mma_kernel,
                         cudaFuncAttributeMaxDynamicSharedMemorySize, PROJ_SMEM);
    cudaFuncSetAttribute(attn_mma_kernel,
                         cudaFuncAttributeMaxDynamicSharedMemorySize, ATTN_SMEM);

    dim3 gsplit(512, 1, 6);
    split_kernel<<<gsplit, 256>>>(q, k, v, Wq, Wk, Wv);

    dim3 gproj(HIDDEN / 128, (TT * BATCH) / 128, 3);
    proj_mma_kernel<<<gproj, 256, PROJ_SMEM>>>(bq, bk, bv);

    dim3 gattn(TT / 128, BATCH * NUM_HEADS);
    attn_mma_kernel<<<gattn, 128, ATTN_SMEM>>>(out);
}